// round 9
// baseline (speedup 1.0000x reference)
#include <cuda_runtime.h>
#include <cuda_bf16.h>

// LocalAttentionLayer: per (l,m): scores[s] = q[l]·K[l,m,s] + (!mask)*-1e7,
// softmax over S=64, pooled[v] = sum_s w[s]*V[l,m,s,v].
// Shapes: L=1024, M=16, S=64, E=Ev=128. HBM-streaming problem (~1.07 GB read).
// Single kernel; mask dtype detected in-kernel per warp (L2-broadcast head read).
// NOTE (R8 lesson): keep register footprint small — occupancy carries the
// latency hiding here; no cross-barrier prefetch arrays.

#define MASK_VALUE -10000000.0f
#define S_DIM 64
#define E_DIM 128
#define M_DIM 16

__global__ void __launch_bounds__(128, 8) local_attn_kernel(
    const float* __restrict__ Q,          // (L, 128)
    const float* __restrict__ K,          // (L, M, 64, 128)
    const float* __restrict__ V,          // (L, M, 64, 128)
    const void*  __restrict__ Mk,         // (L, M, 64) bool, dtype unknown
    float* __restrict__ pooled,           // (L, M, 128)
    float* __restrict__ attn)             // (L, M, 64) or nullptr
{
    const int b    = blockIdx.x;      // l*M + m
    const int l    = b >> 4;          // / M_DIM
    const int tid  = threadIdx.x;
    const int lane = tid & 31;
    const int warp = tid >> 5;
    const size_t base = (size_t)b * S_DIM * E_DIM;

    __shared__ float  sc[S_DIM];
    __shared__ float4 part[4][32];

    // ---- In-kernel mask dtype detection (per warp; no barrier needed). ----
    // 32 words from the mask head (same lines for every CTA -> L2 broadcast).
    // bool-as-uint8: P(all 32 words <= 1) = 8^-32 ~ 0.
    // int32 0/1: every word in {0,1}.  float32 0/1: every word in {0,0x3F800000}.
    const unsigned int mx32 = ((const unsigned int*)Mk)[lane];
    const bool w_not01    = __ballot_sync(0xffffffffu, mx32 > 1u) != 0u;
    const bool w_notfloat = __ballot_sync(0xffffffffu,
                              mx32 != 0u && mx32 != 0x3F800000u) != 0u;
    const int mode = !w_not01 ? 1 : (!w_notfloat ? 2 : 0);  // 1=i32, 2=f32, 0=u8

    // q row: lane holds 4 contiguous elements (same load in all 4 warps; L1/L2 hit)
    const float4 q4 = reinterpret_cast<const float4*>(Q + (size_t)l * E_DIM)[lane];

    // ---- Phase 1: scores. Each warp computes 16 scores (K streamed once). ----
    #pragma unroll
    for (int i = 0; i < 16; ++i) {
        const int s = warp * 16 + i;
        const float4 k4 = __ldcs(
            reinterpret_cast<const float4*>(K + base + (size_t)s * E_DIM) + lane);
        float p = q4.x * k4.x + q4.y * k4.y + q4.z * k4.z + q4.w * k4.w;
        p += __shfl_xor_sync(0xffffffffu, p, 16);
        p += __shfl_xor_sync(0xffffffffu, p, 8);
        p += __shfl_xor_sync(0xffffffffu, p, 4);
        p += __shfl_xor_sync(0xffffffffu, p, 2);
        p += __shfl_xor_sync(0xffffffffu, p, 1);
        if (lane == 0) {
            const size_t midx = (size_t)b * S_DIM + s;
            bool valid;
            if (mode == 0)      valid = ((const unsigned char*)Mk)[midx] != 0;
            else if (mode == 1) valid = ((const int*)Mk)[midx] != 0;
            else                valid = ((const float*)Mk)[midx] != 0.0f;
            sc[s] = p + (valid ? 0.0f : MASK_VALUE);
        }
    }
    __syncthreads();

    // ---- Softmax over 64 scores (warp 0) ----
    if (warp == 0) {
        float a0 = sc[lane];
        float a1 = sc[lane + 32];
        float mxv = fmaxf(a0, a1);
        #pragma unroll
        for (int off = 16; off >= 1; off >>= 1)
            mxv = fmaxf(mxv, __shfl_xor_sync(0xffffffffu, mxv, off));
        float e0 = expf(a0 - mxv);
        float e1 = expf(a1 - mxv);
        float sm = e0 + e1;
        #pragma unroll
        for (int off = 16; off >= 1; off >>= 1)
            sm += __shfl_xor_sync(0xffffffffu, sm, off);
        const float inv = 1.0f / sm;
        e0 *= inv;
        e1 *= inv;
        sc[lane]      = e0;
        sc[lane + 32] = e1;
        if (attn) {
            attn[(size_t)b * S_DIM + lane]      = e0;
            attn[(size_t)b * S_DIM + lane + 32] = e1;
        }
    }
    __syncthreads();

    // ---- Phase 2: pooled = sum_s w[s] * V[s][:]  (V streamed once, float4).
    // Thread: channel group = lane, warp w handles s in [16w, 16w+16).
    {
        float4 acc = make_float4(0.f, 0.f, 0.f, 0.f);
        const float4* Vrow = reinterpret_cast<const float4*>(V + base) + lane;
        #pragma unroll
        for (int i = 0; i < 16; ++i) {
            const int s = warp * 16 + i;
            const float4 v4 = __ldcs(Vrow + (size_t)s * (E_DIM / 4));
            const float  w  = sc[s];
            acc.x += w * v4.x;
            acc.y += w * v4.y;
            acc.z += w * v4.z;
            acc.w += w * v4.w;
        }
        part[warp][lane] = acc;
    }
    __syncthreads();

    // Cross-warp reduce + coalesced 512B store (one warp).
    if (warp == 0) {
        float4 r0 = part[0][lane];
        const float4 r1 = part[1][lane];
        const float4 r2 = part[2][lane];
        const float4 r3 = part[3][lane];
        r0.x += r1.x + r2.x + r3.x;
        r0.y += r1.y + r2.y + r3.y;
        r0.z += r1.z + r2.z + r3.z;
        r0.w += r1.w + r2.w + r3.w;
        reinterpret_cast<float4*>(pooled + (size_t)b * E_DIM)[lane] = r0;
    }
}

extern "C" void kernel_launch(void* const* d_in, const int* in_sizes, int n_in,
                              void* d_out, int out_size) {
    // Positional wiring per setup_inputs() insertion order (validated R5/R6):
    //   d_in[0]=queries, d_in[1]=keys, d_in[2]=values, d_in[3]=attention_mask
    const float* Q  = (const float*)d_in[0];
    const float* K  = (const float*)d_in[1];
    const float* V  = (const float*)d_in[2];
    const void*  Mk = d_in[3];

    const int LM = 1024 * M_DIM;  // 16384

    float* pooled = (float*)d_out;
    float* attn = (out_size >= LM * (E_DIM + S_DIM)) ? pooled + (size_t)LM * E_DIM
                                                     : nullptr;

    local_attn_kernel<<<LM, 128>>>(Q, K, V, Mk, pooled, attn);
}

// round 11
// speedup vs baseline: 1.2777x; 1.2777x over previous
#include <cuda_runtime.h>
#include <cuda_bf16.h>

// LocalAttentionLayer: per (l,m): scores[s] = q[l]·K[l,m,s] + (!mask)*-1e7,
// softmax over S=64, pooled[v] = sum_s w[s]*V[l,m,s,v].
// Shapes: L=1024, M=16, S=64, E=Ev=128. HBM-streaming problem (~1.07 GB read).
// Single kernel; mask dtype detected in-kernel per warp (L2-broadcast head read).
//
// R8/R9 lesson: __launch_bounds__ min-blocks=8 gave ptxas a 64-reg budget; it
// used it and halved occupancy (48%) and bandwidth (67%). min-blocks=16 forces
// the 32-reg / 16-CTA/SM configuration that hit 85% of HBM in R6.

#define MASK_VALUE -10000000.0f
#define S_DIM 64
#define E_DIM 128
#define M_DIM 16

__global__ void __launch_bounds__(128, 16) local_attn_kernel(
    const float* __restrict__ Q,          // (L, 128)
    const float* __restrict__ K,          // (L, M, 64, 128)
    const float* __restrict__ V,          // (L, M, 64, 128)
    const void*  __restrict__ Mk,         // (L, M, 64) bool, dtype unknown
    float* __restrict__ pooled,           // (L, M, 128)
    float* __restrict__ attn)             // (L, M, 64) or nullptr
{
    const int b    = blockIdx.x;      // l*M + m
    const int l    = b >> 4;          // / M_DIM
    const int tid  = threadIdx.x;
    const int lane = tid & 31;
    const int warp = tid >> 5;
    const size_t base = (size_t)b * S_DIM * E_DIM;

    __shared__ float  sc[S_DIM];
    __shared__ float4 part[4][32];

    // ---- In-kernel mask dtype detection (per warp; no barrier needed). ----
    // 32 words from the mask head (same lines for every CTA -> L2 broadcast).
    // bool-as-uint8: P(all 32 words <= 1) = 8^-32 ~ 0.
    // int32 0/1: every word in {0,1}.  float32 0/1: every word in {0,0x3F800000}.
    const unsigned int mx32 = ((const unsigned int*)Mk)[lane];
    const bool w_not01    = __ballot_sync(0xffffffffu, mx32 > 1u) != 0u;
    const bool w_notfloat = __ballot_sync(0xffffffffu,
                              mx32 != 0u && mx32 != 0x3F800000u) != 0u;
    const int mode = !w_not01 ? 1 : (!w_notfloat ? 2 : 0);  // 1=i32, 2=f32, 0=u8

    // q row: lane holds 4 contiguous elements (same load in all 4 warps; L1/L2 hit)
    const float4 q4 = reinterpret_cast<const float4*>(Q + (size_t)l * E_DIM)[lane];

    // ---- Phase 1: scores. Each warp computes 16 scores (K streamed once). ----
    #pragma unroll
    for (int i = 0; i < 16; ++i) {
        const int s = warp * 16 + i;
        const float4 k4 = __ldcs(
            reinterpret_cast<const float4*>(K + base + (size_t)s * E_DIM) + lane);
        float p = q4.x * k4.x + q4.y * k4.y + q4.z * k4.z + q4.w * k4.w;
        p += __shfl_xor_sync(0xffffffffu, p, 16);
        p += __shfl_xor_sync(0xffffffffu, p, 8);
        p += __shfl_xor_sync(0xffffffffu, p, 4);
        p += __shfl_xor_sync(0xffffffffu, p, 2);
        p += __shfl_xor_sync(0xffffffffu, p, 1);
        if (lane == 0) {
            const size_t midx = (size_t)b * S_DIM + s;
            bool valid;
            if (mode == 0)      valid = ((const unsigned char*)Mk)[midx] != 0;
            else if (mode == 1) valid = ((const int*)Mk)[midx] != 0;
            else                valid = ((const float*)Mk)[midx] != 0.0f;
            sc[s] = p + (valid ? 0.0f : MASK_VALUE);
        }
    }
    __syncthreads();

    // ---- Softmax over 64 scores (warp 0) ----
    if (warp == 0) {
        float a0 = sc[lane];
        float a1 = sc[lane + 32];
        float mxv = fmaxf(a0, a1);
        #pragma unroll
        for (int off = 16; off >= 1; off >>= 1)
            mxv = fmaxf(mxv, __shfl_xor_sync(0xffffffffu, mxv, off));
        float e0 = expf(a0 - mxv);
        float e1 = expf(a1 - mxv);
        float sm = e0 + e1;
        #pragma unroll
        for (int off = 16; off >= 1; off >>= 1)
            sm += __shfl_xor_sync(0xffffffffu, sm, off);
        const float inv = 1.0f / sm;
        e0 *= inv;
        e1 *= inv;
        sc[lane]      = e0;
        sc[lane + 32] = e1;
        if (attn) {
            attn[(size_t)b * S_DIM + lane]      = e0;
            attn[(size_t)b * S_DIM + lane + 32] = e1;
        }
    }
    __syncthreads();

    // ---- Phase 2: pooled = sum_s w[s] * V[s][:]  (V streamed once, float4).
    // Thread: channel group = lane, warp w handles s in [16w, 16w+16).
    {
        float4 acc = make_float4(0.f, 0.f, 0.f, 0.f);
        const float4* Vrow = reinterpret_cast<const float4*>(V + base) + lane;
        #pragma unroll
        for (int i = 0; i < 16; ++i) {
            const int s = warp * 16 + i;
            const float4 v4 = __ldcs(Vrow + (size_t)s * (E_DIM / 4));
            const float  w  = sc[s];
            acc.x += w * v4.x;
            acc.y += w * v4.y;
            acc.z += w * v4.z;
            acc.w += w * v4.w;
        }
        part[warp][lane] = acc;
    }
    __syncthreads();

    // Cross-warp reduce + coalesced 512B store (one warp).
    if (warp == 0) {
        float4 r0 = part[0][lane];
        const float4 r1 = part[1][lane];
        const float4 r2 = part[2][lane];
        const float4 r3 = part[3][lane];
        r0.x += r1.x + r2.x + r3.x;
        r0.y += r1.y + r2.y + r3.y;
        r0.z += r1.z + r2.z + r3.z;
        r0.w += r1.w + r2.w + r3.w;
        reinterpret_cast<float4*>(pooled + (size_t)b * E_DIM)[lane] = r0;
    }
}

extern "C" void kernel_launch(void* const* d_in, const int* in_sizes, int n_in,
                              void* d_out, int out_size) {
    // Positional wiring per setup_inputs() insertion order (validated R5/R6):
    //   d_in[0]=queries, d_in[1]=keys, d_in[2]=values, d_in[3]=attention_mask
    const float* Q  = (const float*)d_in[0];
    const float* K  = (const float*)d_in[1];
    const float* V  = (const float*)d_in[2];
    const void*  Mk = d_in[3];

    const int LM = 1024 * M_DIM;  // 16384

    float* pooled = (float*)d_out;
    float* attn = (out_size >= LM * (E_DIM + S_DIM)) ? pooled + (size_t)LM * E_DIM
                                                     : nullptr;

    local_attn_kernel<<<LM, 128>>>(Q, K, V, Mk, pooled, attn);
}